// round 1
// baseline (speedup 1.0000x reference)
#include <cuda_runtime.h>
#include <math.h>

#define Bc  2
#define Sc  2048
#define Dc  1024
#define Hc  16
#define HDc 64

// Scratch (allocation-free): head-major [B*H][S][HD] layouts.
__device__ float g_q[Bc*Sc*Dc];
__device__ float g_k[Bc*Sc*Dc];
__device__ float g_v[Bc*Sc*Dc];
__device__ float g_g[Bc*Sc*Dc];

// ---------------------------------------------------------------------------
// Projection GEMM: Y[m,n] = sum_k X[m,k]*W[n,k] + b[n]   (M=4096, N=K=1024)
// blockIdx.z selects which of the 4 weight matrices; output written in
// [b][h][s][hd] head-major layout for the attention kernel.
// 128x128 tile, BK=16, 256 threads, 8x8 per thread.
// ---------------------------------------------------------------------------
__global__ __launch_bounds__(256)
void proj_kernel(const float* __restrict__ x,
                 const float* __restrict__ Wq, const float* __restrict__ bq,
                 const float* __restrict__ Wk, const float* __restrict__ bk,
                 const float* __restrict__ Wv, const float* __restrict__ bv,
                 const float* __restrict__ Wg, const float* __restrict__ bg)
{
    const float* W; const float* bias; float* dst;
    if (blockIdx.z == 0)      { W = Wq; bias = bq; dst = g_q; }
    else if (blockIdx.z == 1) { W = Wk; bias = bk; dst = g_k; }
    else if (blockIdx.z == 2) { W = Wv; bias = bv; dst = g_v; }
    else                      { W = Wg; bias = bg; dst = g_g; }

    __shared__ float Xs[16][132];   // [k][m], pad 132 -> light store conflicts
    __shared__ float Ws[16][132];   // [k][n]

    const int tid = threadIdx.x;
    const int ty  = tid >> 4;       // 0..15 (row group)
    const int tx  = tid & 15;       // 0..15 (col group)
    const int m0  = blockIdx.y * 128;
    const int n0  = blockIdx.x * 128;

    float acc[8][8] = {};

    for (int k0 = 0; k0 < Dc; k0 += 16) {
        #pragma unroll
        for (int r = 0; r < 2; r++) {
            int f   = tid + 256 * r;
            int row = f >> 2;
            int c4  = (f & 3) * 4;
            float4 xa = *(const float4*)(x + (size_t)(m0 + row) * Dc + k0 + c4);
            float4 wa = *(const float4*)(W + (size_t)(n0 + row) * Dc + k0 + c4);
            Xs[c4+0][row] = xa.x; Xs[c4+1][row] = xa.y;
            Xs[c4+2][row] = xa.z; Xs[c4+3][row] = xa.w;
            Ws[c4+0][row] = wa.x; Ws[c4+1][row] = wa.y;
            Ws[c4+2][row] = wa.z; Ws[c4+3][row] = wa.w;
        }
        __syncthreads();
        #pragma unroll
        for (int k = 0; k < 16; k++) {
            float a[8], bb[8];
            *(float4*)&a[0]  = *(const float4*)&Xs[k][ty*8];
            *(float4*)&a[4]  = *(const float4*)&Xs[k][ty*8+4];
            *(float4*)&bb[0] = *(const float4*)&Ws[k][tx*8];
            *(float4*)&bb[4] = *(const float4*)&Ws[k][tx*8+4];
            #pragma unroll
            for (int i = 0; i < 8; i++)
                #pragma unroll
                for (int j = 0; j < 8; j++)
                    acc[i][j] = fmaf(a[i], bb[j], acc[i][j]);
        }
        __syncthreads();
    }

    float bv8[8];
    #pragma unroll
    for (int j = 0; j < 8; j++) bv8[j] = bias[n0 + tx*8 + j];

    const int h  = (n0 + tx*8) >> 6;   // head index (8 cols never cross a head)
    const int d0 = (n0 + tx*8) & 63;   // dim within head
    #pragma unroll
    for (int i = 0; i < 8; i++) {
        int m  = m0 + ty*8 + i;
        int b_ = m >> 11;
        int s_ = m & 2047;
        float* p = dst + ((size_t)(b_ * Hc + h) * Sc + s_) * HDc + d0;
        float4 v0, v1;
        v0.x = acc[i][0] + bv8[0]; v0.y = acc[i][1] + bv8[1];
        v0.z = acc[i][2] + bv8[2]; v0.w = acc[i][3] + bv8[3];
        v1.x = acc[i][4] + bv8[4]; v1.y = acc[i][5] + bv8[5];
        v1.z = acc[i][6] + bv8[6]; v1.w = acc[i][7] + bv8[7];
        *(float4*)p       = v0;
        *(float4*)(p + 4) = v1;
    }
}

// ---------------------------------------------------------------------------
// Gate: qg = gelu_exact(q * g), in-place into g_q.
// ---------------------------------------------------------------------------
__device__ __forceinline__ float gelu_exact(float x) {
    return 0.5f * x * (1.0f + erff(x * 0.7071067811865476f));
}

__global__ __launch_bounds__(256)
void gate_kernel()
{
    int i = blockIdx.x * blockDim.x + threadIdx.x;   // exactly B*S*D/4 threads
    float4 q = ((const float4*)g_q)[i];
    float4 g = ((const float4*)g_g)[i];
    float4 r;
    r.x = gelu_exact(q.x * g.x);
    r.y = gelu_exact(q.y * g.y);
    r.z = gelu_exact(q.z * g.z);
    r.w = gelu_exact(q.w * g.w);
    ((float4*)g_q)[i] = r;
}

// ---------------------------------------------------------------------------
// Flash attention: one (bh, q-tile of 64) per block. 128 threads (16x8),
// each thread owns a 4x8 fragment of the 64x64 score tile and of O.
// Smem: Qs [d][m] (64x64), KP = K^T [d][n] / P [n][m] aliased (64x65 pad),
//       Vs [n][d] (64x64).  Total 49408 B dynamic.
// ---------------------------------------------------------------------------
__global__ __launch_bounds__(128)
void attn_kernel(float* __restrict__ out)
{
    extern __shared__ float sm[];
    float* Qs = sm;                  // 4096 floats, [d*64 + m]
    float* KP = sm + 4096;           // 4160 floats, stride 65
    float* Vs = sm + 4096 + 4160;    // 4096 floats, [n*64 + d]

    const int tid = threadIdx.x;
    const int ty  = tid >> 3;        // 0..15 -> rows ty*4..ty*4+3
    const int tx  = tid & 7;         // 0..7  -> cols tx*8..tx*8+7
    const int qt  = blockIdx.x;      // 0..31 query tile
    const int bh  = blockIdx.y;      // 0..31 (b*16 + h)

    const float* Q = g_q + (size_t)bh * Sc * HDc + (size_t)qt * 64 * HDc;
    const float* K = g_k + (size_t)bh * Sc * HDc;
    const float* V = g_v + (size_t)bh * Sc * HDc;

    // Load Q tile transposed: Qs[d][m]. 32 consecutive threads -> 32 distinct m
    // (conflict-free smem stores).
    {
        int m  = tid & 63;
        int dg = tid >> 6;           // 0..1
        #pragma unroll
        for (int it = 0; it < 8; it++) {
            int d4 = (dg + it * 2) * 4;
            float4 qv = *(const float4*)(Q + (size_t)m * HDc + d4);
            Qs[(d4+0)*64 + m] = qv.x;
            Qs[(d4+1)*64 + m] = qv.y;
            Qs[(d4+2)*64 + m] = qv.z;
            Qs[(d4+3)*64 + m] = qv.w;
        }
    }

    float o[4][8] = {};
    float mrow[4] = {-1e30f, -1e30f, -1e30f, -1e30f};
    float lrow[4] = {};

    __syncthreads();

    for (int kt = 0; kt < Sc / 64; kt++) {
        const float* Kt = K + (size_t)kt * 64 * HDc;
        const float* Vt = V + (size_t)kt * 64 * HDc;

        // K tile transposed into KP [d][n], stride 65 (conflict-free stores).
        {
            int n  = tid & 63;
            int dg = tid >> 6;
            #pragma unroll
            for (int it = 0; it < 8; it++) {
                int d4 = (dg + it * 2) * 4;
                float4 kv = *(const float4*)(Kt + (size_t)n * HDc + d4);
                KP[(d4+0)*65 + n] = kv.x;
                KP[(d4+1)*65 + n] = kv.y;
                KP[(d4+2)*65 + n] = kv.z;
                KP[(d4+3)*65 + n] = kv.w;
            }
        }
        // V tile natural [n][d] — fully coalesced float4 both sides.
        {
            int dg = (tid & 15) * 4;
            int nb = tid >> 4;
            #pragma unroll
            for (int it = 0; it < 8; it++) {
                int n = nb + it * 8;
                *(float4*)&Vs[n*64 + dg] = *(const float4*)(Vt + (size_t)n * HDc + dg);
            }
        }
        __syncthreads();

        // S = Qg @ K^T  (64x64x64)
        float sc[4][8] = {};
        #pragma unroll
        for (int d = 0; d < 64; d++) {
            float qf[4], kf[8];
            *(float4*)qf = *(const float4*)&Qs[d*64 + ty*4];
            #pragma unroll
            for (int j = 0; j < 8; j++) kf[j] = KP[d*65 + tx*8 + j];
            #pragma unroll
            for (int i = 0; i < 4; i++)
                #pragma unroll
                for (int j = 0; j < 8; j++)
                    sc[i][j] = fmaf(qf[i], kf[j], sc[i][j]);
        }
        __syncthreads();   // all K reads done before P overwrites KP

        // Online softmax update + stage P transposed into KP [n][m].
        #pragma unroll
        for (int i = 0; i < 4; i++) {
            float mx = sc[i][0];
            #pragma unroll
            for (int j = 1; j < 8; j++) mx = fmaxf(mx, sc[i][j]);
            mx = fmaxf(mx, __shfl_xor_sync(0xffffffffu, mx, 1));
            mx = fmaxf(mx, __shfl_xor_sync(0xffffffffu, mx, 2));
            mx = fmaxf(mx, __shfl_xor_sync(0xffffffffu, mx, 4));
            float mnew  = fmaxf(mrow[i], mx);
            float scale = expf(mrow[i] - mnew);
            mrow[i] = mnew;
            float rs = 0.f;
            #pragma unroll
            for (int j = 0; j < 8; j++) {
                float p = expf(sc[i][j] - mnew);
                sc[i][j] = p;
                rs += p;
            }
            rs += __shfl_xor_sync(0xffffffffu, rs, 1);
            rs += __shfl_xor_sync(0xffffffffu, rs, 2);
            rs += __shfl_xor_sync(0xffffffffu, rs, 4);
            lrow[i] = lrow[i] * scale + rs;
            #pragma unroll
            for (int j = 0; j < 8; j++) o[i][j] *= scale;
            #pragma unroll
            for (int j = 0; j < 8; j++)
                KP[(tx*8 + j)*65 + ty*4 + i] = sc[i][j];
        }
        __syncthreads();   // P fully staged

        // O += P @ V  (64x64x64)
        #pragma unroll
        for (int n = 0; n < 64; n++) {
            float pf[4], vf[8];
            #pragma unroll
            for (int i = 0; i < 4; i++) pf[i] = KP[n*65 + ty*4 + i];
            *(float4*)&vf[0] = *(const float4*)&Vs[n*64 + tx*8];
            *(float4*)&vf[4] = *(const float4*)&Vs[n*64 + tx*8 + 4];
            #pragma unroll
            for (int i = 0; i < 4; i++)
                #pragma unroll
                for (int j = 0; j < 8; j++)
                    o[i][j] = fmaf(pf[i], vf[j], o[i][j]);
        }
        __syncthreads();   // PV reads done before next tile load
    }

    // Epilogue: normalize and write [B,S,D] output.
    const int b_ = bh >> 4;
    const int h  = bh & 15;
    #pragma unroll
    for (int i = 0; i < 4; i++) {
        int s_ = qt * 64 + ty*4 + i;
        float inv = 1.0f / lrow[i];
        float4 r0, r1;
        r0.x = o[i][0]*inv; r0.y = o[i][1]*inv; r0.z = o[i][2]*inv; r0.w = o[i][3]*inv;
        r1.x = o[i][4]*inv; r1.y = o[i][5]*inv; r1.z = o[i][6]*inv; r1.w = o[i][7]*inv;
        float* p = out + ((size_t)b_ * Sc + s_) * Dc + h * 64 + tx*8;
        *(float4*)p       = r0;
        *(float4*)(p + 4) = r1;
    }
}

// ---------------------------------------------------------------------------
extern "C" void kernel_launch(void* const* d_in, const int* in_sizes, int n_in,
                              void* d_out, int out_size)
{
    const float* x  = (const float*)d_in[0];
    const float* Wq = (const float*)d_in[1];
    const float* bq = (const float*)d_in[2];
    const float* Wk = (const float*)d_in[3];
    const float* bk = (const float*)d_in[4];
    const float* Wv = (const float*)d_in[5];
    const float* bv = (const float*)d_in[6];
    const float* Wg = (const float*)d_in[7];
    const float* bg = (const float*)d_in[8];
    float* out = (float*)d_out;

    // 4 projections in one launch: grid (N/128, M/128, 4)
    dim3 gp(Dc / 128, (Bc * Sc) / 128, 4);
    proj_kernel<<<gp, 256>>>(x, Wq, bq, Wk, bk, Wv, bv, Wg, bg);

    // qg = gelu(q*g): exactly B*S*D/4 float4 elements
    gate_kernel<<<(Bc * Sc * Dc / 4) / 256, 256>>>();

    // flash attention
    const int smem = (4096 + 4160 + 4096) * (int)sizeof(float);  // 49408
    cudaFuncSetAttribute((const void*)attn_kernel,
                         cudaFuncAttributeMaxDynamicSharedMemorySize, smem);
    attn_kernel<<<dim3(Sc / 64, Bc * Hc), 128, smem>>>(out);
}

// round 3
// speedup vs baseline: 3.9980x; 3.9980x over previous
#include <cuda_runtime.h>
#include <math.h>
#include <stdint.h>

#define Bc  2
#define Sc  2048
#define Dc  1024
#define Hc  16
#define HDc 64

// Scratch (allocation-free): head-major [B*H][S][HD] layouts.
__device__ float g_q[Bc*Sc*Dc];
__device__ float g_k[Bc*Sc*Dc];
__device__ float g_v[Bc*Sc*Dc];
__device__ float g_g[Bc*Sc*Dc];

// ---------------------------------------------------------------------------
// tf32 helpers (arch-agnostic PTX, sm_80+: legal in compute_103)
// ---------------------------------------------------------------------------
__device__ __forceinline__ uint32_t tf32c(float f) {
    uint32_t u;
    asm("cvt.rna.tf32.f32 %0, %1;" : "=r"(u) : "f"(f));
    return u;
}

// D += A(16x8,row) * B(8x8,col); tf32 inputs, fp32 accumulate.
__device__ __forceinline__ void mma8(float c[4], const uint32_t a[4],
                                     uint32_t b0, uint32_t b1) {
    asm volatile(
        "mma.sync.aligned.m16n8k8.row.col.f32.tf32.tf32.f32 "
        "{%0,%1,%2,%3}, {%4,%5,%6,%7}, {%8,%9}, {%0,%1,%2,%3};"
        : "+f"(c[0]), "+f"(c[1]), "+f"(c[2]), "+f"(c[3])
        : "r"(a[0]), "r"(a[1]), "r"(a[2]), "r"(a[3]), "r"(b0), "r"(b1));
}

// ===========================================================================
// Projection GEMM (tf32 mma.sync): Y[m,n] = sum_k X[m,k]*W[n,k] + b[n]
// M=4096, N=K=1024 per matrix; blockIdx.z selects matrix. Output head-major.
// Tile 128x128, BK=32, 8 warps (4m x 2n), warp tile 32x64 (2x8 mma tiles).
// Smem [row][k] stride 36 (36 mod 32 = 4 -> conflict-free fragment loads).
// ===========================================================================
__global__ __launch_bounds__(256)
void proj_mma(const float* __restrict__ x,
              const float* __restrict__ Wq, const float* __restrict__ bq,
              const float* __restrict__ Wk, const float* __restrict__ bk,
              const float* __restrict__ Wv, const float* __restrict__ bv,
              const float* __restrict__ Wg, const float* __restrict__ bg)
{
    __shared__ uint32_t Xs[128 * 36];
    __shared__ uint32_t Wsm[128 * 36];

    const float* W; const float* bias; float* dst;
    if (blockIdx.z == 0)      { W = Wq; bias = bq; dst = g_q; }
    else if (blockIdx.z == 1) { W = Wk; bias = bk; dst = g_k; }
    else if (blockIdx.z == 2) { W = Wv; bias = bv; dst = g_v; }
    else                      { W = Wg; bias = bg; dst = g_g; }

    const int tid  = threadIdx.x;
    const int lane = tid & 31;
    const int wid  = tid >> 5;
    const int wm   = wid & 3;       // 4 warps along M (32 rows each)
    const int wn   = wid >> 2;      // 2 warps along N (64 cols each)
    const int m0   = blockIdx.y * 128;
    const int n0   = blockIdx.x * 128;
    const int lq   = lane >> 2;     // 0..7
    const int lr   = lane & 3;      // 0..3

    float acc[2][8][4] = {};

    for (int k0 = 0; k0 < Dc; k0 += 32) {
        // Stage X and W tiles (cvt to tf32, vectorized stores).
        #pragma unroll
        for (int r = 0; r < 4; r++) {
            int f   = tid + 256 * r;     // 0..1023
            int row = f >> 3;            // 0..127
            int c4  = f & 7;             // 0..7
            float4 xa = *(const float4*)(x + (size_t)(m0 + row) * Dc + k0 + c4 * 4);
            float4 wa = *(const float4*)(W + (size_t)(n0 + row) * Dc + k0 + c4 * 4);
            uint4 xt = { tf32c(xa.x), tf32c(xa.y), tf32c(xa.z), tf32c(xa.w) };
            uint4 wt = { tf32c(wa.x), tf32c(wa.y), tf32c(wa.z), tf32c(wa.w) };
            *(uint4*)&Xs[row * 36 + c4 * 4]  = xt;
            *(uint4*)&Wsm[row * 36 + c4 * 4] = wt;
        }
        __syncthreads();

        #pragma unroll
        for (int kk = 0; kk < 4; kk++) {
            const int kb = kk * 8 + lr;
            uint32_t a[2][4];
            #pragma unroll
            for (int mi = 0; mi < 2; mi++) {
                int rb = (wm * 32 + mi * 16 + lq) * 36;
                a[mi][0] = Xs[rb + kb];
                a[mi][1] = Xs[rb + 8 * 36 + kb];
                a[mi][2] = Xs[rb + kb + 4];
                a[mi][3] = Xs[rb + 8 * 36 + kb + 4];
            }
            #pragma unroll
            for (int ni = 0; ni < 8; ni++) {
                int nb = (wn * 64 + ni * 8 + lq) * 36 + kb;
                uint32_t b0 = Wsm[nb];
                uint32_t b1 = Wsm[nb + 4];
                mma8(acc[0][ni], a[0], b0, b1);
                mma8(acc[1][ni], a[1], b0, b1);
            }
        }
        __syncthreads();
    }

    // Epilogue: bias add + head-major scatter (float2 stores).
    #pragma unroll
    for (int ni = 0; ni < 8; ni++) {
        int col = n0 + wn * 64 + ni * 8 + lr * 2;
        float bx = bias[col], by = bias[col + 1];
        int h  = col >> 6;
        int d0 = col & 63;
        #pragma unroll
        for (int mi = 0; mi < 2; mi++) {
            int mA = m0 + wm * 32 + mi * 16 + lq;
            int mB = mA + 8;
            int bA = mA >> 11, sA = mA & 2047;
            int bB = mB >> 11, sB = mB & 2047;
            float2 vA = { acc[mi][ni][0] + bx, acc[mi][ni][1] + by };
            float2 vB = { acc[mi][ni][2] + bx, acc[mi][ni][3] + by };
            *(float2*)(dst + ((size_t)(bA * Hc + h) * Sc + sA) * HDc + d0) = vA;
            *(float2*)(dst + ((size_t)(bB * Hc + h) * Sc + sB) * HDc + d0) = vB;
        }
    }
}

// ---------------------------------------------------------------------------
// Gate: qg = gelu_exact(q * g), in-place into g_q.
// ---------------------------------------------------------------------------
__device__ __forceinline__ float gelu_exact(float x) {
    return 0.5f * x * (1.0f + erff(x * 0.7071067811865476f));
}

__global__ __launch_bounds__(256)
void gate_kernel()
{
    int i = blockIdx.x * blockDim.x + threadIdx.x;
    float4 q = ((const float4*)g_q)[i];
    float4 g = ((const float4*)g_g)[i];
    float4 r;
    r.x = gelu_exact(q.x * g.x);
    r.y = gelu_exact(q.y * g.y);
    r.z = gelu_exact(q.z * g.z);
    r.w = gelu_exact(q.w * g.w);
    ((float4*)g_q)[i] = r;
}

// ===========================================================================
// Flash attention (tf32 mma.sync).
// Block: 128 threads (4 warps), q-tile 128 (warp owns 32 q = 2 m-tiles),
// token-tile 64, d = 64.
// Smem (uint32 tf32 bits): Qs [q][d] s68, Ks [t][d] s68, Vs [t][d] s72,
// Ps [q][t] s68. Strides chosen for conflict-free fragment loads.
// ===========================================================================
#define QS_OFF 0
#define KS_OFF (128*68)                    // 8704
#define VS_OFF (KS_OFF + 64*68)            // 13056
#define PS_OFF (VS_OFF + 64*72)            // 17664
#define ATTN_SMEM_U32 (PS_OFF + 128*68)    // 26368 u32 = 105472 B

__global__ __launch_bounds__(128)
void attn_mma(float* __restrict__ out)
{
    extern __shared__ uint32_t sm[];
    uint32_t* Qs = sm + QS_OFF;
    uint32_t* Ks = sm + KS_OFF;
    uint32_t* Vs = sm + VS_OFF;
    uint32_t* Ps = sm + PS_OFF;

    const int tid  = threadIdx.x;
    const int lane = tid & 31;
    const int wid  = tid >> 5;      // 0..3, warp owns q rows wid*32..wid*32+31
    const int lq   = lane >> 2;     // 0..7
    const int lr   = lane & 3;      // 0..3
    const int qt   = blockIdx.x;    // 0..15 (128-row q tiles)
    const int bh   = blockIdx.y;    // 0..31

    const float* Q = g_q + (size_t)bh * Sc * HDc + (size_t)qt * 128 * HDc;
    const float* K = g_k + (size_t)bh * Sc * HDc;
    const float* V = g_v + (size_t)bh * Sc * HDc;

    // Stage Q once: [q][d] tf32, one row per thread (16 float4).
    {
        const float* qrow = Q + (size_t)tid * HDc;
        #pragma unroll
        for (int c = 0; c < 16; c++) {
            float4 v = *(const float4*)(qrow + c * 4);
            uint4 t = { tf32c(v.x), tf32c(v.y), tf32c(v.z), tf32c(v.w) };
            *(uint4*)&Qs[tid * 68 + c * 4] = t;
        }
    }

    float o[2][8][4] = {};
    float mrow[4] = {-1e30f, -1e30f, -1e30f, -1e30f};  // [mi*2+half]
    float lrow[4] = {};

    __syncthreads();

    for (int kt = 0; kt < Sc / 64; kt++) {
        const float* Kt = K + (size_t)kt * 64 * HDc;
        const float* Vt = V + (size_t)kt * 64 * HDc;

        // Stage K [t][d] s68 and V [t][d] s72 (both natural, vectorized).
        #pragma unroll
        for (int r = 0; r < 8; r++) {
            int f   = tid + 128 * r;        // 0..1023
            int row = f >> 4;               // 0..63
            int c4  = f & 15;               // 0..15
            float4 kv = *(const float4*)(Kt + (size_t)row * HDc + c4 * 4);
            float4 vv = *(const float4*)(Vt + (size_t)row * HDc + c4 * 4);
            uint4 ktb = { tf32c(kv.x), tf32c(kv.y), tf32c(kv.z), tf32c(kv.w) };
            uint4 vtb = { tf32c(vv.x), tf32c(vv.y), tf32c(vv.z), tf32c(vv.w) };
            *(uint4*)&Ks[row * 68 + c4 * 4] = ktb;
            *(uint4*)&Vs[row * 72 + c4 * 4] = vtb;
        }
        __syncthreads();

        // S = Qg @ K^T : warp tile 32q x 64t, k-dim = d = 64 (8 ksteps).
        float sc[2][8][4] = {};
        #pragma unroll
        for (int kk = 0; kk < 8; kk++) {
            const int kb = kk * 8 + lr;
            uint32_t a[2][4];
            #pragma unroll
            for (int mi = 0; mi < 2; mi++) {
                int rb = (wid * 32 + mi * 16 + lq) * 68;
                a[mi][0] = Qs[rb + kb];
                a[mi][1] = Qs[rb + 8 * 68 + kb];
                a[mi][2] = Qs[rb + kb + 4];
                a[mi][3] = Qs[rb + 8 * 68 + kb + 4];
            }
            #pragma unroll
            for (int ni = 0; ni < 8; ni++) {
                int nb = (ni * 8 + lq) * 68 + kb;   // B elem (d=kb, t=ni*8+lq)
                uint32_t b0 = Ks[nb];
                uint32_t b1 = Ks[nb + 4];
                mma8(sc[0][ni], a[0], b0, b1);
                mma8(sc[1][ni], a[1], b0, b1);
            }
        }

        // Online softmax per row; stage P (tf32) into Ps[q][t].
        #pragma unroll
        for (int mi = 0; mi < 2; mi++) {
            #pragma unroll
            for (int half = 0; half < 2; half++) {
                const int st = half * 2;           // sc[..][st], sc[..][st+1]
                const int ridx = mi * 2 + half;
                float mx = -1e30f;
                #pragma unroll
                for (int ni = 0; ni < 8; ni++)
                    mx = fmaxf(mx, fmaxf(sc[mi][ni][st], sc[mi][ni][st + 1]));
                mx = fmaxf(mx, __shfl_xor_sync(0xffffffffu, mx, 1));
                mx = fmaxf(mx, __shfl_xor_sync(0xffffffffu, mx, 2));
                float mnew  = fmaxf(mrow[ridx], mx);
                float scale = __expf(mrow[ridx] - mnew);
                mrow[ridx]  = mnew;
                float rs = 0.f;
                const int prow = (wid * 32 + mi * 16 + half * 8 + lq) * 68;
                #pragma unroll
                for (int ni = 0; ni < 8; ni++) {
                    float p0 = __expf(sc[mi][ni][st]     - mnew);
                    float p1 = __expf(sc[mi][ni][st + 1] - mnew);
                    rs += p0 + p1;
                    uint2 pb = { tf32c(p0), tf32c(p1) };
                    *(uint2*)&Ps[prow + ni * 8 + lr * 2] = pb;
                }
                rs += __shfl_xor_sync(0xffffffffu, rs, 1);
                rs += __shfl_xor_sync(0xffffffffu, rs, 2);
                lrow[ridx] = lrow[ridx] * scale + rs;
                #pragma unroll
                for (int ni = 0; ni < 8; ni++) {
                    o[mi][ni][st]     *= scale;
                    o[mi][ni][st + 1] *= scale;
                }
            }
        }
        __syncwarp();   // P staged (own-warp region only)

        // O += P @ V : k-dim = tokens = 64 (8 ksteps), n-dim = d = 64.
        #pragma unroll
        for (int kk = 0; kk < 8; kk++) {
            const int kb = kk * 8 + lr;
            uint32_t a[2][4];
            #pragma unroll
            for (int mi = 0; mi < 2; mi++) {
                int rb = (wid * 32 + mi * 16 + lq) * 68;
                a[mi][0] = Ps[rb + kb];
                a[mi][1] = Ps[rb + 8 * 68 + kb];
                a[mi][2] = Ps[rb + kb + 4];
                a[mi][3] = Ps[rb + 8 * 68 + kb + 4];
            }
            #pragma unroll
            for (int ni = 0; ni < 8; ni++) {
                int nb0 = (kk * 8 + lr) * 72 + ni * 8 + lq;  // V elem (t, d)
                uint32_t b0 = Vs[nb0];
                uint32_t b1 = Vs[nb0 + 4 * 72];
                mma8(o[0][ni], a[0], b0, b1);
                mma8(o[1][ni], a[1], b0, b1);
            }
        }
        __syncthreads();   // all reads of Ks/Vs done before next staging
    }

    // Epilogue: normalize, write [B,S,D].
    const int b_ = bh >> 4;
    const int h  = bh & 15;
    #pragma unroll
    for (int mi = 0; mi < 2; mi++) {
        #pragma unroll
        for (int half = 0; half < 2; half++) {
            const int st = half * 2;
            float inv = 1.0f / lrow[mi * 2 + half];
            int s_ = qt * 128 + wid * 32 + mi * 16 + half * 8 + lq;
            float* orow = out + ((size_t)b_ * Sc + s_) * Dc + h * 64;
            #pragma unroll
            for (int ni = 0; ni < 8; ni++) {
                float2 v = { o[mi][ni][st] * inv, o[mi][ni][st + 1] * inv };
                *(float2*)(orow + ni * 8 + lr * 2) = v;
            }
        }
    }
}

// ---------------------------------------------------------------------------
extern "C" void kernel_launch(void* const* d_in, const int* in_sizes, int n_in,
                              void* d_out, int out_size)
{
    const float* x  = (const float*)d_in[0];
    const float* Wq = (const float*)d_in[1];
    const float* bq = (const float*)d_in[2];
    const float* Wk = (const float*)d_in[3];
    const float* bk = (const float*)d_in[4];
    const float* Wv = (const float*)d_in[5];
    const float* bv = (const float*)d_in[6];
    const float* Wg = (const float*)d_in[7];
    const float* bg = (const float*)d_in[8];
    float* out = (float*)d_out;

    dim3 gp(Dc / 128, (Bc * Sc) / 128, 4);
    proj_mma<<<gp, 256>>>(x, Wq, bq, Wk, bk, Wv, bv, Wg, bg);

    gate_kernel<<<(Bc * Sc * Dc / 4) / 256, 256>>>();

    const int smem = ATTN_SMEM_U32 * (int)sizeof(uint32_t);   // 105472
    cudaFuncSetAttribute((const void*)attn_mma,
                         cudaFuncAttributeMaxDynamicSharedMemorySize, smem);
    attn_mma<<<dim3(Sc / 128, Bc * Hc), 128, smem>>>(out);
}

// round 4
// speedup vs baseline: 7.3000x; 1.8259x over previous
#include <cuda_runtime.h>
#include <cuda_fp16.h>
#include <math.h>
#include <stdint.h>

#define Bc  2
#define Sc  2048
#define Dc  1024
#define Hc  16
#define HDc 64

// Scratch (allocation-free).
__device__ __align__(16) __half g_xh[Bc*Sc*Dc];     // x as fp16 [B*S][D]
__device__ __align__(16) __half g_wh[4*Dc*Dc];      // Wq,Wk,Wv,Wg as fp16 [n][k]
__device__ float               g_qf[Bc*Sc*Dc];      // q proj fp32, head-major
__device__ float               g_gf[Bc*Sc*Dc];      // g proj fp32, head-major
__device__ __align__(16) __half g_qh[Bc*Sc*Dc];     // gelu(q*g) fp16, head-major
__device__ __align__(16) __half g_kh[Bc*Sc*Dc];     // k fp16, head-major
__device__ __align__(16) __half g_vh[Bc*Sc*Dc];     // v fp16, head-major

// ---------------------------------------------------------------------------
// PTX helpers (all sm_80-era, legal in compute_103 PTX)
// ---------------------------------------------------------------------------
__device__ __forceinline__ uint32_t smem_u32(const void* p) {
    uint32_t a;
    asm("{ .reg .u64 t; cvta.to.shared.u64 t, %1; cvt.u32.u64 %0, t; }"
        : "=r"(a) : "l"(p));
    return a;
}

__device__ __forceinline__ void ldsm4(uint32_t r[4], uint32_t addr) {
    asm volatile("ldmatrix.sync.aligned.m8n8.x4.shared.b16 {%0,%1,%2,%3}, [%4];"
                 : "=r"(r[0]), "=r"(r[1]), "=r"(r[2]), "=r"(r[3]) : "r"(addr));
}

__device__ __forceinline__ void ldsm4t(uint32_t r[4], uint32_t addr) {
    asm volatile("ldmatrix.sync.aligned.m8n8.x4.trans.shared.b16 {%0,%1,%2,%3}, [%4];"
                 : "=r"(r[0]), "=r"(r[1]), "=r"(r[2]), "=r"(r[3]) : "r"(addr));
}

// D += A(16x16) * B(16x8); fp16 inputs, fp32 accumulate.
__device__ __forceinline__ void mma16(float c[4], const uint32_t a[4],
                                      uint32_t b0, uint32_t b1) {
    asm volatile(
        "mma.sync.aligned.m16n8k16.row.col.f32.f16.f16.f32 "
        "{%0,%1,%2,%3}, {%4,%5,%6,%7}, {%8,%9}, {%0,%1,%2,%3};"
        : "+f"(c[0]), "+f"(c[1]), "+f"(c[2]), "+f"(c[3])
        : "r"(a[0]), "r"(a[1]), "r"(a[2]), "r"(a[3]), "r"(b0), "r"(b1));
}

__device__ __forceinline__ void cp16(uint32_t dst, const void* src) {
    asm volatile("cp.async.cg.shared.global [%0], [%1], 16;"
                 :: "r"(dst), "l"(src) : "memory");
}
#define CP_COMMIT() asm volatile("cp.async.commit_group;" ::: "memory")
#define CP_WAIT1()  asm volatile("cp.async.wait_group 1;" ::: "memory")
#define CP_WAIT0()  asm volatile("cp.async.wait_group 0;" ::: "memory")

// ---------------------------------------------------------------------------
// Pre-convert x and W to fp16. grid (4096, 5): z=0 -> x, z=1..4 -> W
// ---------------------------------------------------------------------------
__global__ __launch_bounds__(256)
void cvt_kernel(const float* __restrict__ x,
                const float* __restrict__ Wq, const float* __restrict__ Wk,
                const float* __restrict__ Wv, const float* __restrict__ Wg)
{
    int z = blockIdx.y;
    int i = blockIdx.x * 256 + threadIdx.x;     // float4 index
    const float* src; __half* dst; int n4;
    if (z == 0)      { src = x;  dst = g_xh;               n4 = Bc*Sc*Dc/4; }
    else if (z == 1) { src = Wq; dst = g_wh + 0*Dc*Dc;     n4 = Dc*Dc/4; }
    else if (z == 2) { src = Wk; dst = g_wh + 1*Dc*Dc;     n4 = Dc*Dc/4; }
    else if (z == 3) { src = Wv; dst = g_wh + 2*Dc*Dc;     n4 = Dc*Dc/4; }
    else             { src = Wg; dst = g_wh + 3*Dc*Dc;     n4 = Dc*Dc/4; }
    if (i < n4) {
        float4 v = ((const float4*)src)[i];
        ((__half2*)dst)[2*i]   = __floats2half2_rn(v.x, v.y);
        ((__half2*)dst)[2*i+1] = __floats2half2_rn(v.z, v.w);
    }
}

// ===========================================================================
// Projection GEMM (fp16 mma.sync, cp.async double-buffered):
// Y[m,n] = sum_k X[m,k]*W[n,k] + b[n]. 128x128 tile, BK=32, 8 warps (4m x 2n).
// Smem [row][k] fp16 stride 40 halves (80B) -> conflict-free ldmatrix.
// ===========================================================================
#define PR_STRIDE 40
__global__ __launch_bounds__(256, 2)
void proj_h(const float* __restrict__ bq, const float* __restrict__ bk,
            const float* __restrict__ bv, const float* __restrict__ bg)
{
    __shared__ __half Xs[2][128 * PR_STRIDE];
    __shared__ __half Wsm[2][128 * PR_STRIDE];

    const int z = blockIdx.z;
    const __half* Wg_ = g_wh + (size_t)z * Dc * Dc;
    const float* bias = (z == 0) ? bq : (z == 1) ? bk : (z == 2) ? bv : bg;

    const int tid  = threadIdx.x;
    const int lane = tid & 31;
    const int wid  = tid >> 5;
    const int wm   = wid & 3;
    const int wn   = wid >> 2;
    const int m0   = blockIdx.y * 128;
    const int n0   = blockIdx.x * 128;
    const int lq   = lane >> 2;
    const int lr   = lane & 3;

    const uint32_t xb = smem_u32(Xs);
    const uint32_t wb = smem_u32(Wsm);

    const int srow = tid >> 2;          // 0..63 base row (2 phases)
    const int sc4  = tid & 3;           // chunk 0..3

    float acc[2][8][4] = {};

    // prologue: stage tile 0 into buf 0
    #pragma unroll
    for (int r = 0; r < 2; r++) {
        int row = srow + r * 64;
        uint32_t d = (uint32_t)(row * PR_STRIDE + sc4 * 8) * 2;
        cp16(xb + d, g_xh + (size_t)(m0 + row) * Dc + sc4 * 8);
        cp16(wb + d, Wg_ + (size_t)(n0 + row) * Dc + sc4 * 8);
    }
    CP_COMMIT();

    for (int it = 0; it < 32; it++) {
        const int buf = it & 1;
        if (it + 1 < 32) {
            const int k0 = (it + 1) * 32;
            const uint32_t boff = (uint32_t)((buf ^ 1) * 128 * PR_STRIDE) * 2;
            #pragma unroll
            for (int r = 0; r < 2; r++) {
                int row = srow + r * 64;
                uint32_t d = boff + (uint32_t)(row * PR_STRIDE + sc4 * 8) * 2;
                cp16(xb + d, g_xh + (size_t)(m0 + row) * Dc + k0 + sc4 * 8);
                cp16(wb + d, Wg_ + (size_t)(n0 + row) * Dc + k0 + sc4 * 8);
            }
            CP_COMMIT();
            CP_WAIT1();
        } else {
            CP_WAIT0();
        }
        __syncthreads();

        const uint32_t xab = xb + (uint32_t)(buf * 128 * PR_STRIDE) * 2;
        const uint32_t wab = wb + (uint32_t)(buf * 128 * PR_STRIDE) * 2;
        #pragma unroll
        for (int kk = 0; kk < 2; kk++) {
            uint32_t a[2][4];
            #pragma unroll
            for (int mi = 0; mi < 2; mi++) {
                int row = wm * 32 + mi * 16 + (lane & 15);
                ldsm4(a[mi], xab + (uint32_t)(row * PR_STRIDE + kk * 16 + (lane >> 4) * 8) * 2);
            }
            #pragma unroll
            for (int np = 0; np < 4; np++) {
                int g   = lane >> 3;
                int row = wn * 64 + np * 16 + (g >> 1) * 8 + (lane & 7);
                uint32_t bb[4];
                ldsm4(bb, wab + (uint32_t)(row * PR_STRIDE + kk * 16 + (g & 1) * 8) * 2);
                mma16(acc[0][2*np],   a[0], bb[0], bb[1]);
                mma16(acc[1][2*np],   a[1], bb[0], bb[1]);
                mma16(acc[0][2*np+1], a[0], bb[2], bb[3]);
                mma16(acc[1][2*np+1], a[1], bb[2], bb[3]);
            }
        }
        __syncthreads();
    }

    // Epilogue: bias add + head-major scatter. z 0/3 -> fp32 (q,g); 1/2 -> fp16 (k,v).
    #pragma unroll
    for (int ni = 0; ni < 8; ni++) {
        int col = n0 + wn * 64 + ni * 8 + lr * 2;
        float bx = bias[col], by = bias[col + 1];
        int h  = col >> 6;
        int d0 = col & 63;
        #pragma unroll
        for (int mi = 0; mi < 2; mi++) {
            int mA = m0 + wm * 32 + mi * 16 + lq;
            int mB = mA + 8;
            size_t iA = ((size_t)((mA >> 11) * Hc + h) * Sc + (mA & 2047)) * HDc + d0;
            size_t iB = ((size_t)((mB >> 11) * Hc + h) * Sc + (mB & 2047)) * HDc + d0;
            float a0 = acc[mi][ni][0] + bx, a1 = acc[mi][ni][1] + by;
            float a2 = acc[mi][ni][2] + bx, a3 = acc[mi][ni][3] + by;
            if (z == 1) {
                *(__half2*)(g_kh + iA) = __floats2half2_rn(a0, a1);
                *(__half2*)(g_kh + iB) = __floats2half2_rn(a2, a3);
            } else if (z == 2) {
                *(__half2*)(g_vh + iA) = __floats2half2_rn(a0, a1);
                *(__half2*)(g_vh + iB) = __floats2half2_rn(a2, a3);
            } else {
                float* dst = (z == 0) ? g_qf : g_gf;
                *(float2*)(dst + iA) = make_float2(a0, a1);
                *(float2*)(dst + iB) = make_float2(a2, a3);
            }
        }
    }
}

// ---------------------------------------------------------------------------
// Gate: g_qh = fp16(gelu_exact(q * g))
// ---------------------------------------------------------------------------
__device__ __forceinline__ float gelu_exact(float x) {
    return 0.5f * x * (1.0f + erff(x * 0.7071067811865476f));
}

__global__ __launch_bounds__(256)
void gate_kernel()
{
    int i = blockIdx.x * blockDim.x + threadIdx.x;
    float4 q = ((const float4*)g_qf)[i];
    float4 g = ((const float4*)g_gf)[i];
    float r0 = gelu_exact(q.x * g.x);
    float r1 = gelu_exact(q.y * g.y);
    float r2 = gelu_exact(q.z * g.z);
    float r3 = gelu_exact(q.w * g.w);
    ((__half2*)g_qh)[2*i]   = __floats2half2_rn(r0, r1);
    ((__half2*)g_qh)[2*i+1] = __floats2half2_rn(r2, r3);
}

// ===========================================================================
// Flash attention (fp16 mma.sync, cp.async double-buffered K/V).
// Block: 128 threads (4 warps), q-tile 128 (warp: 32q x 64t), token-tile 64.
// Smem halves stride 72 (144B): Qs 128, Ks 2x64, Vs 2x64, Ps 128.
// ===========================================================================
#define AT_S   72
#define QS_H   0
#define KS_H   (128 * AT_S)                 // 9216
#define VS_H   (KS_H + 2 * 64 * AT_S)       // 18432
#define PS_H   (VS_H + 2 * 64 * AT_S)       // 27648
#define AT_SMEM_BYTES ((PS_H + 128 * AT_S) * 2)   // 73728

__global__ __launch_bounds__(128, 3)
void attn_h(float* __restrict__ out)
{
    extern __shared__ __half sh[];
    const uint32_t sb = smem_u32(sh);

    const int tid  = threadIdx.x;
    const int lane = tid & 31;
    const int wid  = tid >> 5;
    const int lq   = lane >> 2;
    const int lr   = lane & 3;
    const int qt   = blockIdx.x;      // 0..15
    const int bh   = blockIdx.y;      // 0..31

    const __half* Qg = g_qh + ((size_t)bh * Sc + (size_t)qt * 128) * HDc;
    const __half* Kg = g_kh + (size_t)bh * Sc * HDc;
    const __half* Vg = g_vh + (size_t)bh * Sc * HDc;

    // Stage Q (once) + KV tile 0, all in cp.async group 0.
    #pragma unroll
    for (int c = 0; c < 8; c++)
        cp16(sb + (uint32_t)(QS_H + tid * AT_S + c * 8) * 2,
             Qg + (size_t)tid * HDc + c * 8);
    {
        const int srow = tid >> 3;      // 0..15 base row (4 phases of 16)
        const int sc8  = tid & 7;
        #pragma unroll
        for (int r = 0; r < 4; r++) {
            int row = srow + r * 16;
            uint32_t d = (uint32_t)(row * AT_S + sc8 * 8) * 2;
            cp16(sb + (KS_H) * 2 + d, Kg + (size_t)row * HDc + sc8 * 8);
            cp16(sb + (VS_H) * 2 + d, Vg + (size_t)row * HDc + sc8 * 8);
        }
    }
    CP_COMMIT();

    float o[2][8][4] = {};
    float mrow[4] = {-1e30f, -1e30f, -1e30f, -1e30f};
    float lrow[4] = {};

    for (int kt = 0; kt < Sc / 64; kt++) {
        const int buf = kt & 1;
        if (kt + 1 < Sc / 64) {
            const int srow = tid >> 3;
            const int sc8  = tid & 7;
            const uint32_t boff = (uint32_t)((buf ^ 1) * 64 * AT_S) * 2;
            const __half* Kt = Kg + (size_t)(kt + 1) * 64 * HDc;
            const __half* Vt = Vg + (size_t)(kt + 1) * 64 * HDc;
            #pragma unroll
            for (int r = 0; r < 4; r++) {
                int row = srow + r * 16;
                uint32_t d = (uint32_t)(row * AT_S + sc8 * 8) * 2;
                cp16(sb + KS_H * 2 + boff + d, Kt + (size_t)row * HDc + sc8 * 8);
                cp16(sb + VS_H * 2 + boff + d, Vt + (size_t)row * HDc + sc8 * 8);
            }
            CP_COMMIT();
            CP_WAIT1();
        } else {
            CP_WAIT0();
        }
        __syncthreads();

        const uint32_t kab = sb + (uint32_t)(KS_H + buf * 64 * AT_S) * 2;
        const uint32_t vab = sb + (uint32_t)(VS_H + buf * 64 * AT_S) * 2;

        // S = Q @ K^T : 32q x 64t, k = d = 64 (4 k16 steps)
        float scf[2][8][4] = {};
        #pragma unroll
        for (int kk = 0; kk < 4; kk++) {
            uint32_t a[2][4];
            #pragma unroll
            for (int mi = 0; mi < 2; mi++) {
                int row = wid * 32 + mi * 16 + (lane & 15);
                ldsm4(a[mi], sb + (uint32_t)(QS_H + row * AT_S + kk * 16 + (lane >> 4) * 8) * 2);
            }
            #pragma unroll
            for (int np = 0; np < 4; np++) {
                int g   = lane >> 3;
                int row = np * 16 + (g >> 1) * 8 + (lane & 7);
                uint32_t bb[4];
                ldsm4(bb, kab + (uint32_t)(row * AT_S + kk * 16 + (g & 1) * 8) * 2);
                mma16(scf[0][2*np],   a[0], bb[0], bb[1]);
                mma16(scf[1][2*np],   a[1], bb[0], bb[1]);
                mma16(scf[0][2*np+1], a[0], bb[2], bb[3]);
                mma16(scf[1][2*np+1], a[1], bb[2], bb[3]);
            }
        }

        // Online softmax; stage P (fp16) into Ps[q][t].
        #pragma unroll
        for (int mi = 0; mi < 2; mi++) {
            #pragma unroll
            for (int half = 0; half < 2; half++) {
                const int st = half * 2;
                const int ridx = mi * 2 + half;
                float mx = -1e30f;
                #pragma unroll
                for (int ni = 0; ni < 8; ni++)
                    mx = fmaxf(mx, fmaxf(scf[mi][ni][st], scf[mi][ni][st + 1]));
                mx = fmaxf(mx, __shfl_xor_sync(0xffffffffu, mx, 1));
                mx = fmaxf(mx, __shfl_xor_sync(0xffffffffu, mx, 2));
                float mnew  = fmaxf(mrow[ridx], mx);
                float scale = __expf(mrow[ridx] - mnew);
                mrow[ridx]  = mnew;
                float rs = 0.f;
                const int prow = wid * 32 + mi * 16 + half * 8 + lq;
                #pragma unroll
                for (int ni = 0; ni < 8; ni++) {
                    float p0 = __expf(scf[mi][ni][st]     - mnew);
                    float p1 = __expf(scf[mi][ni][st + 1] - mnew);
                    rs += p0 + p1;
                    *(__half2*)(sh + PS_H + prow * AT_S + ni * 8 + lr * 2) =
                        __floats2half2_rn(p0, p1);
                }
                rs += __shfl_xor_sync(0xffffffffu, rs, 1);
                rs += __shfl_xor_sync(0xffffffffu, rs, 2);
                lrow[ridx] = lrow[ridx] * scale + rs;
                #pragma unroll
                for (int ni = 0; ni < 8; ni++) {
                    o[mi][ni][st]     *= scale;
                    o[mi][ni][st + 1] *= scale;
                }
            }
        }
        __syncwarp();   // P staged (own-warp rows only)

        // O += P @ V : k = tokens = 64 (4 k16 steps), V via ldmatrix.trans.
        #pragma unroll
        for (int kk = 0; kk < 4; kk++) {
            uint32_t a[2][4];
            #pragma unroll
            for (int mi = 0; mi < 2; mi++) {
                int row = wid * 32 + mi * 16 + (lane & 15);
                ldsm4(a[mi], sb + (uint32_t)(PS_H + row * AT_S + kk * 16 + (lane >> 4) * 8) * 2);
            }
            #pragma unroll
            for (int np = 0; np < 4; np++) {
                int row   = kk * 16 + ((lane >> 3) & 1) * 8 + (lane & 7);
                int chunk = np * 2 + (lane >> 4);
                uint32_t bb[4];
                ldsm4t(bb, vab + (uint32_t)(row * AT_S + chunk * 8) * 2);
                mma16(o[0][2*np],   a[0], bb[0], bb[1]);
                mma16(o[1][2*np],   a[1], bb[0], bb[1]);
                mma16(o[0][2*np+1], a[0], bb[2], bb[3]);
                mma16(o[1][2*np+1], a[1], bb[2], bb[3]);
            }
        }
        __syncthreads();
    }

    // Epilogue: normalize, write [B,S,D].
    const int b_ = bh >> 4;
    const int h  = bh & 15;
    #pragma unroll
    for (int mi = 0; mi < 2; mi++) {
        #pragma unroll
        for (int half = 0; half < 2; half++) {
            const int st = half * 2;
            float inv = 1.0f / lrow[mi * 2 + half];
            int s_ = qt * 128 + wid * 32 + mi * 16 + half * 8 + lq;
            float* orow = out + ((size_t)b_ * Sc + s_) * Dc + h * 64;
            #pragma unroll
            for (int ni = 0; ni < 8; ni++) {
                float2 v = { o[mi][ni][st] * inv, o[mi][ni][st + 1] * inv };
                *(float2*)(orow + ni * 8 + lr * 2) = v;
            }
        }
    }
}

// ---------------------------------------------------------------------------
extern "C" void kernel_launch(void* const* d_in, const int* in_sizes, int n_in,
                              void* d_out, int out_size)
{
    const float* x  = (const float*)d_in[0];
    const float* Wq = (const float*)d_in[1];
    const float* bq = (const float*)d_in[2];
    const float* Wk = (const float*)d_in[3];
    const float* bk = (const float*)d_in[4];
    const float* Wv = (const float*)d_in[5];
    const float* bv = (const float*)d_in[6];
    const float* Wg = (const float*)d_in[7];
    const float* bg = (const float*)d_in[8];
    float* out = (float*)d_out;

    cvt_kernel<<<dim3(4096, 5), 256>>>(x, Wq, Wk, Wv, Wg);

    dim3 gp(Dc / 128, (Bc * Sc) / 128, 4);
    proj_h<<<gp, 256>>>(bq, bk, bv, bg);

    gate_kernel<<<(Bc * Sc * Dc / 4) / 256, 256>>>();

    cudaFuncSetAttribute((const void*)attn_h,
                         cudaFuncAttributeMaxDynamicSharedMemorySize, AT_SMEM_BYTES);
    attn_h<<<dim3(Sc / 128, Bc * Hc), 128, AT_SMEM_BYTES>>>(out);
}

// round 5
// speedup vs baseline: 7.5847x; 1.0390x over previous
#include <cuda_runtime.h>
#include <cuda_fp16.h>
#include <math.h>
#include <stdint.h>

#define Bc  2
#define Sc  2048
#define Dc  1024
#define Hc  16
#define HDc 64

// Scratch (allocation-free).
__device__ __align__(16) __half g_xh[Bc*Sc*Dc];     // x as fp16 [B*S][D]
__device__ __align__(16) __half g_wh[4*Dc*Dc];      // Wq,Wk,Wv,Wg as fp16 [n][k]
__device__ float               g_qf[Bc*Sc*Dc];      // q proj fp32, head-major
__device__ float               g_gf[Bc*Sc*Dc];      // g proj fp32, head-major
__device__ __align__(16) __half g_kh[Bc*Sc*Dc];     // k fp16, head-major
__device__ __align__(16) __half g_vh[Bc*Sc*Dc];     // v fp16, head-major

// ---------------------------------------------------------------------------
// PTX helpers (all sm_80-era, legal in compute_103 PTX)
// ---------------------------------------------------------------------------
__device__ __forceinline__ uint32_t smem_u32(const void* p) {
    uint32_t a;
    asm("{ .reg .u64 t; cvta.to.shared.u64 t, %1; cvt.u32.u64 %0, t; }"
        : "=r"(a) : "l"(p));
    return a;
}

__device__ __forceinline__ void ldsm4(uint32_t r[4], uint32_t addr) {
    asm volatile("ldmatrix.sync.aligned.m8n8.x4.shared.b16 {%0,%1,%2,%3}, [%4];"
                 : "=r"(r[0]), "=r"(r[1]), "=r"(r[2]), "=r"(r[3]) : "r"(addr));
}

__device__ __forceinline__ void ldsm4t(uint32_t r[4], uint32_t addr) {
    asm volatile("ldmatrix.sync.aligned.m8n8.x4.trans.shared.b16 {%0,%1,%2,%3}, [%4];"
                 : "=r"(r[0]), "=r"(r[1]), "=r"(r[2]), "=r"(r[3]) : "r"(addr));
}

// D += A(16x16) * B(16x8); fp16 inputs, fp32 accumulate.
__device__ __forceinline__ void mma16(float c[4], const uint32_t a[4],
                                      uint32_t b0, uint32_t b1) {
    asm volatile(
        "mma.sync.aligned.m16n8k16.row.col.f32.f16.f16.f32 "
        "{%0,%1,%2,%3}, {%4,%5,%6,%7}, {%8,%9}, {%0,%1,%2,%3};"
        : "+f"(c[0]), "+f"(c[1]), "+f"(c[2]), "+f"(c[3])
        : "r"(a[0]), "r"(a[1]), "r"(a[2]), "r"(a[3]), "r"(b0), "r"(b1));
}

__device__ __forceinline__ void cp16(uint32_t dst, const void* src) {
    asm volatile("cp.async.cg.shared.global [%0], [%1], 16;"
                 :: "r"(dst), "l"(src) : "memory");
}
#define CP_COMMIT() asm volatile("cp.async.commit_group;" ::: "memory")
#define CP_WAIT1()  asm volatile("cp.async.wait_group 1;" ::: "memory")
#define CP_WAIT0()  asm volatile("cp.async.wait_group 0;" ::: "memory")

__device__ __forceinline__ uint32_t packh2(float a, float b) {
    __half2 h = __floats2half2_rn(a, b);
    return *reinterpret_cast<uint32_t*>(&h);
}

// ---------------------------------------------------------------------------
// Pre-convert x and W to fp16. grid (4096, 5): z=0 -> x, z=1..4 -> W
// ---------------------------------------------------------------------------
__global__ __launch_bounds__(256)
void cvt_kernel(const float* __restrict__ x,
                const float* __restrict__ Wq, const float* __restrict__ Wk,
                const float* __restrict__ Wv, const float* __restrict__ Wg)
{
    int z = blockIdx.y;
    int i = blockIdx.x * 256 + threadIdx.x;     // float4 index
    const float* src; __half* dst; int n4;
    if (z == 0)      { src = x;  dst = g_xh;               n4 = Bc*Sc*Dc/4; }
    else if (z == 1) { src = Wq; dst = g_wh + 0*Dc*Dc;     n4 = Dc*Dc/4; }
    else if (z == 2) { src = Wk; dst = g_wh + 1*Dc*Dc;     n4 = Dc*Dc/4; }
    else if (z == 3) { src = Wv; dst = g_wh + 2*Dc*Dc;     n4 = Dc*Dc/4; }
    else             { src = Wg; dst = g_wh + 3*Dc*Dc;     n4 = Dc*Dc/4; }
    if (i < n4) {
        float4 v = ((const float4*)src)[i];
        ((__half2*)dst)[2*i]   = __floats2half2_rn(v.x, v.y);
        ((__half2*)dst)[2*i+1] = __floats2half2_rn(v.z, v.w);
    }
}

// ===========================================================================
// Projection GEMM (fp16 mma.sync, cp.async double-buffered):
// Y[m,n] = sum_k X[m,k]*W[n,k] + b[n]. 128x128 tile, BK=32, 8 warps (4m x 2n).
// ===========================================================================
#define PR_STRIDE 40
__global__ __launch_bounds__(256, 2)
void proj_h(const float* __restrict__ bq, const float* __restrict__ bk,
            const float* __restrict__ bv, const float* __restrict__ bg)
{
    __shared__ __half Xs[2][128 * PR_STRIDE];
    __shared__ __half Wsm[2][128 * PR_STRIDE];

    const int z = blockIdx.z;
    const __half* Wg_ = g_wh + (size_t)z * Dc * Dc;
    const float* bias = (z == 0) ? bq : (z == 1) ? bk : (z == 2) ? bv : bg;

    const int tid  = threadIdx.x;
    const int lane = tid & 31;
    const int wid  = tid >> 5;
    const int wm   = wid & 3;
    const int wn   = wid >> 2;
    const int m0   = blockIdx.y * 128;
    const int n0   = blockIdx.x * 128;
    const int lq   = lane >> 2;
    const int lr   = lane & 3;

    const uint32_t xb = smem_u32(Xs);
    const uint32_t wb = smem_u32(Wsm);

    const int srow = tid >> 2;
    const int sc4  = tid & 3;

    float acc[2][8][4] = {};

    #pragma unroll
    for (int r = 0; r < 2; r++) {
        int row = srow + r * 64;
        uint32_t d = (uint32_t)(row * PR_STRIDE + sc4 * 8) * 2;
        cp16(xb + d, g_xh + (size_t)(m0 + row) * Dc + sc4 * 8);
        cp16(wb + d, Wg_ + (size_t)(n0 + row) * Dc + sc4 * 8);
    }
    CP_COMMIT();

    for (int it = 0; it < 32; it++) {
        const int buf = it & 1;
        if (it + 1 < 32) {
            const int k0 = (it + 1) * 32;
            const uint32_t boff = (uint32_t)((buf ^ 1) * 128 * PR_STRIDE) * 2;
            #pragma unroll
            for (int r = 0; r < 2; r++) {
                int row = srow + r * 64;
                uint32_t d = boff + (uint32_t)(row * PR_STRIDE + sc4 * 8) * 2;
                cp16(xb + d, g_xh + (size_t)(m0 + row) * Dc + k0 + sc4 * 8);
                cp16(wb + d, Wg_ + (size_t)(n0 + row) * Dc + k0 + sc4 * 8);
            }
            CP_COMMIT();
            CP_WAIT1();
        } else {
            CP_WAIT0();
        }
        __syncthreads();

        const uint32_t xab = xb + (uint32_t)(buf * 128 * PR_STRIDE) * 2;
        const uint32_t wab = wb + (uint32_t)(buf * 128 * PR_STRIDE) * 2;
        #pragma unroll
        for (int kk = 0; kk < 2; kk++) {
            uint32_t a[2][4];
            #pragma unroll
            for (int mi = 0; mi < 2; mi++) {
                int row = wm * 32 + mi * 16 + (lane & 15);
                ldsm4(a[mi], xab + (uint32_t)(row * PR_STRIDE + kk * 16 + (lane >> 4) * 8) * 2);
            }
            #pragma unroll
            for (int np = 0; np < 4; np++) {
                int g   = lane >> 3;
                int row = wn * 64 + np * 16 + (g >> 1) * 8 + (lane & 7);
                uint32_t bb[4];
                ldsm4(bb, wab + (uint32_t)(row * PR_STRIDE + kk * 16 + (g & 1) * 8) * 2);
                mma16(acc[0][2*np],   a[0], bb[0], bb[1]);
                mma16(acc[1][2*np],   a[1], bb[0], bb[1]);
                mma16(acc[0][2*np+1], a[0], bb[2], bb[3]);
                mma16(acc[1][2*np+1], a[1], bb[2], bb[3]);
            }
        }
        __syncthreads();
    }

    // Epilogue: bias add + head-major scatter. z 0/3 -> fp32 (q,g); 1/2 -> fp16 (k,v).
    #pragma unroll
    for (int ni = 0; ni < 8; ni++) {
        int col = n0 + wn * 64 + ni * 8 + lr * 2;
        float bx = bias[col], by = bias[col + 1];
        int h  = col >> 6;
        int d0 = col & 63;
        #pragma unroll
        for (int mi = 0; mi < 2; mi++) {
            int mA = m0 + wm * 32 + mi * 16 + lq;
            int mB = mA + 8;
            size_t iA = ((size_t)((mA >> 11) * Hc + h) * Sc + (mA & 2047)) * HDc + d0;
            size_t iB = ((size_t)((mB >> 11) * Hc + h) * Sc + (mB & 2047)) * HDc + d0;
            float a0 = acc[mi][ni][0] + bx, a1 = acc[mi][ni][1] + by;
            float a2 = acc[mi][ni][2] + bx, a3 = acc[mi][ni][3] + by;
            if (z == 1) {
                *(__half2*)(g_kh + iA) = __floats2half2_rn(a0, a1);
                *(__half2*)(g_kh + iB) = __floats2half2_rn(a2, a3);
            } else if (z == 2) {
                *(__half2*)(g_vh + iA) = __floats2half2_rn(a0, a1);
                *(__half2*)(g_vh + iB) = __floats2half2_rn(a2, a3);
            } else {
                float* dst = (z == 0) ? g_qf : g_gf;
                *(float2*)(dst + iA) = make_float2(a0, a1);
                *(float2*)(dst + iB) = make_float2(a2, a3);
            }
        }
    }
}

// ---------------------------------------------------------------------------
__device__ __forceinline__ float gelu_exact(float x) {
    return 0.5f * x * (1.0f + erff(x * 0.7071067811865476f));
}

// ===========================================================================
// Flash attention (fp16 mma.sync, register-resident P, fused gelu gate).
// Block: 128 threads (4 warps), q-tile 128 (warp: 32q x 64t), token-tile 64.
// Smem halves stride 72: Qs 128 rows, Ks 2x64, Vs 2x64. 55296 B total.
// ===========================================================================
#define AT_S   72
#define QS_H   0
#define KS_H   (128 * AT_S)                 // 9216
#define VS_H   (KS_H + 2 * 64 * AT_S)       // 18432
#define AT_SMEM_BYTES ((VS_H + 2 * 64 * AT_S) * 2)   // 55296

__global__ __launch_bounds__(128, 3)
void attn_h(float* __restrict__ out)
{
    extern __shared__ __half sh[];
    const uint32_t sb = smem_u32(sh);

    const int tid  = threadIdx.x;
    const int lane = tid & 31;
    const int wid  = tid >> 5;
    const int lq   = lane >> 2;
    const int lr   = lane & 3;
    const int qt   = blockIdx.x;      // 0..15
    const int bh   = blockIdx.y;      // 0..31

    const float* Qf = g_qf + ((size_t)bh * Sc + (size_t)qt * 128) * HDc;
    const float* Gf = g_gf + ((size_t)bh * Sc + (size_t)qt * 128) * HDc;
    const __half* Kg = g_kh + (size_t)bh * Sc * HDc;
    const __half* Vg = g_vh + (size_t)bh * Sc * HDc;

    // Stage Q with fused gate: qg = gelu(q*g), fp16 into Qs. One row/thread.
    {
        const float* qrow = Qf + (size_t)tid * HDc;
        const float* grow = Gf + (size_t)tid * HDc;
        #pragma unroll
        for (int c = 0; c < 16; c++) {
            float4 qv = *(const float4*)(qrow + c * 4);
            float4 gv = *(const float4*)(grow + c * 4);
            uint2 pk;
            pk.x = packh2(gelu_exact(qv.x * gv.x), gelu_exact(qv.y * gv.y));
            pk.y = packh2(gelu_exact(qv.z * gv.z), gelu_exact(qv.w * gv.w));
            *(uint2*)(sh + QS_H + tid * AT_S + c * 4) = pk;
        }
    }
    // KV tile 0 via cp.async.
    {
        const int srow = tid >> 3;
        const int sc8  = tid & 7;
        #pragma unroll
        for (int r = 0; r < 4; r++) {
            int row = srow + r * 16;
            uint32_t d = (uint32_t)(row * AT_S + sc8 * 8) * 2;
            cp16(sb + KS_H * 2 + d, Kg + (size_t)row * HDc + sc8 * 8);
            cp16(sb + VS_H * 2 + d, Vg + (size_t)row * HDc + sc8 * 8);
        }
    }
    CP_COMMIT();

    float o[2][8][4] = {};
    float mrow[4] = {-1e30f, -1e30f, -1e30f, -1e30f};
    float lrow[4] = {};

    for (int kt = 0; kt < Sc / 64; kt++) {
        const int buf = kt & 1;
        if (kt + 1 < Sc / 64) {
            const int srow = tid >> 3;
            const int sc8  = tid & 7;
            const uint32_t boff = (uint32_t)((buf ^ 1) * 64 * AT_S) * 2;
            const __half* Kt = Kg + (size_t)(kt + 1) * 64 * HDc;
            const __half* Vt = Vg + (size_t)(kt + 1) * 64 * HDc;
            #pragma unroll
            for (int r = 0; r < 4; r++) {
                int row = srow + r * 16;
                uint32_t d = (uint32_t)(row * AT_S + sc8 * 8) * 2;
                cp16(sb + KS_H * 2 + boff + d, Kt + (size_t)row * HDc + sc8 * 8);
                cp16(sb + VS_H * 2 + boff + d, Vt + (size_t)row * HDc + sc8 * 8);
            }
            CP_COMMIT();
            CP_WAIT1();
        } else {
            CP_WAIT0();
        }
        __syncthreads();

        const uint32_t kab = sb + (uint32_t)(KS_H + buf * 64 * AT_S) * 2;
        const uint32_t vab = sb + (uint32_t)(VS_H + buf * 64 * AT_S) * 2;

        // S = Q @ K^T : 32q x 64t, k = d = 64 (4 k16 steps)
        float scf[2][8][4] = {};
        #pragma unroll
        for (int kk = 0; kk < 4; kk++) {
            uint32_t a[2][4];
            #pragma unroll
            for (int mi = 0; mi < 2; mi++) {
                int row = wid * 32 + mi * 16 + (lane & 15);
                ldsm4(a[mi], sb + (uint32_t)(QS_H + row * AT_S + kk * 16 + (lane >> 4) * 8) * 2);
            }
            #pragma unroll
            for (int np = 0; np < 4; np++) {
                int g   = lane >> 3;
                int row = np * 16 + (g >> 1) * 8 + (lane & 7);
                uint32_t bb[4];
                ldsm4(bb, kab + (uint32_t)(row * AT_S + kk * 16 + (g & 1) * 8) * 2);
                mma16(scf[0][2*np],   a[0], bb[0], bb[1]);
                mma16(scf[1][2*np],   a[1], bb[0], bb[1]);
                mma16(scf[0][2*np+1], a[0], bb[2], bb[3]);
                mma16(scf[1][2*np+1], a[1], bb[2], bb[3]);
            }
        }

        // Online softmax; pack P directly into PV A-fragments (register P).
        // A-frag layout for k-step kk (tokens 16kk..16kk+15):
        //   pf[mi][kk][0]=(lq, ni=2kk) pf[1]=(lq+8, ni=2kk)
        //   pf[2]=(lq, ni=2kk+1)       pf[3]=(lq+8, ni=2kk+1)
        uint32_t pf[2][4][4];
        #pragma unroll
        for (int mi = 0; mi < 2; mi++) {
            #pragma unroll
            for (int half = 0; half < 2; half++) {
                const int st = half * 2;
                const int ridx = mi * 2 + half;
                float mx = -1e30f;
                #pragma unroll
                for (int ni = 0; ni < 8; ni++)
                    mx = fmaxf(mx, fmaxf(scf[mi][ni][st], scf[mi][ni][st + 1]));
                mx = fmaxf(mx, __shfl_xor_sync(0xffffffffu, mx, 1));
                mx = fmaxf(mx, __shfl_xor_sync(0xffffffffu, mx, 2));
                float mnew  = fmaxf(mrow[ridx], mx);
                float scale = __expf(mrow[ridx] - mnew);
                mrow[ridx]  = mnew;
                float rs = 0.f;
                #pragma unroll
                for (int ni = 0; ni < 8; ni++) {
                    float p0 = __expf(scf[mi][ni][st]     - mnew);
                    float p1 = __expf(scf[mi][ni][st + 1] - mnew);
                    rs += p0 + p1;
                    pf[mi][ni >> 1][(ni & 1) * 2 + half] = packh2(p0, p1);
                }
                rs += __shfl_xor_sync(0xffffffffu, rs, 1);
                rs += __shfl_xor_sync(0xffffffffu, rs, 2);
                lrow[ridx] = lrow[ridx] * scale + rs;
                #pragma unroll
                for (int ni = 0; ni < 8; ni++) {
                    o[mi][ni][st]     *= scale;
                    o[mi][ni][st + 1] *= scale;
                }
            }
        }

        // O += P @ V : k = tokens = 64 (4 k16 steps), V via ldmatrix.trans.
        #pragma unroll
        for (int kk = 0; kk < 4; kk++) {
            #pragma unroll
            for (int np = 0; np < 4; np++) {
                int row   = kk * 16 + ((lane >> 3) & 1) * 8 + (lane & 7);
                int chunk = np * 2 + (lane >> 4);
                uint32_t bb[4];
                ldsm4t(bb, vab + (uint32_t)(row * AT_S + chunk * 8) * 2);
                mma16(o[0][2*np],   pf[0][kk], bb[0], bb[1]);
                mma16(o[1][2*np],   pf[1][kk], bb[0], bb[1]);
                mma16(o[0][2*np+1], pf[0][kk], bb[2], bb[3]);
                mma16(o[1][2*np+1], pf[1][kk], bb[2], bb[3]);
            }
        }
        __syncthreads();
    }

    // Epilogue: normalize, write [B,S,D].
    const int b_ = bh >> 4;
    const int h  = bh & 15;
    #pragma unroll
    for (int mi = 0; mi < 2; mi++) {
        #pragma unroll
        for (int half = 0; half < 2; half++) {
            const int st = half * 2;
            float inv = 1.0f / lrow[mi * 2 + half];
            int s_ = qt * 128 + wid * 32 + mi * 16 + half * 8 + lq;
            float* orow = out + ((size_t)b_ * Sc + s_) * Dc + h * 64;
            #pragma unroll
            for (int ni = 0; ni < 8; ni++) {
                float2 v = { o[mi][ni][st] * inv, o[mi][ni][st + 1] * inv };
                *(float2*)(orow + ni * 8 + lr * 2) = v;
            }
        }
    }
}

// ---------------------------------------------------------------------------
extern "C" void kernel_launch(void* const* d_in, const int* in_sizes, int n_in,
                              void* d_out, int out_size)
{
    const float* x  = (const float*)d_in[0];
    const float* Wq = (const float*)d_in[1];
    const float* bq = (const float*)d_in[2];
    const float* Wk = (const float*)d_in[3];
    const float* bk = (const float*)d_in[4];
    const float* Wv = (const float*)d_in[5];
    const float* bv = (const float*)d_in[6];
    const float* Wg = (const float*)d_in[7];
    const float* bg = (const float*)d_in[8];
    float* out = (float*)d_out;

    cvt_kernel<<<dim3(4096, 5), 256>>>(x, Wq, Wk, Wv, Wg);

    dim3 gp(Dc / 128, (Bc * Sc) / 128, 4);
    proj_h<<<gp, 256>>>(bq, bk, bv, bg);

    cudaFuncSetAttribute((const void*)attn_h,
                         cudaFuncAttributeMaxDynamicSharedMemorySize, AT_SMEM_BYTES);
    attn_h<<<dim3(Sc / 128, Bc * Hc), 128, AT_SMEM_BYTES>>>(out);
}